// round 9
// baseline (speedup 1.0000x reference)
#include <cuda_runtime.h>
#include <cuda_bf16.h>

// KuramotoDaidoMeanField — closed-form evaluation, R9: fully FP64-free.
//
// Math (derived R5): s' = s*m(s), m(s)-1 = C(s-s_inf)(s-r2); trajectory phase
// sum = Abel/Euler-Maclaurin rational integral with exact partial fractions
// + 3-pt Gauss correction + endpoint term.
//
// R9 precision scheme (no doubles anywhere):
//  - phi_inf = -asin(c) exactly (b_inf^2 + c^2 = 1). Split as -(c + t),
//    c exact float, t = c^3*(1/6 + 3c^2/40 + 15c^4/336) ~ 2e-5 (float ok).
//  - n*c kept exact as a float pair: P_hi = n*c, P_lo = fmaf(n,c,-P_hi).
//  - mod 2*pi via Cody-Waite with (twopi_hi, twopi_lo) float pair and exact
//    fma folding. Total phase error ~2e-6 << method truncation ~4e-5.

#define DT 0.01f

__device__ __forceinline__ float atan_small_f(float y)
{
    const float y2 = y * y;
    float p = -1.0f / 7.0f;
    p = __fmaf_rn(p, y2,  1.0f / 5.0f);
    p = __fmaf_rn(p, y2, -1.0f / 3.0f);
    p = __fmaf_rn(p, y2,  1.0f);
    return y * p;
}

__device__ __forceinline__ float log1p_small_f(float x)
{
    float p =  1.0f / 5.0f;
    p = __fmaf_rn(p, x, -1.0f / 4.0f);
    p = __fmaf_rn(p, x,  1.0f / 3.0f);
    p = __fmaf_rn(p, x, -1.0f / 2.0f);
    return x * __fmaf_rn(p, x, 1.0f);
}

__global__ void kuramoto_kernel(const float* __restrict__ omega_mean,
                                const float* __restrict__ coupling,
                                const float* __restrict__ delta,
                                const float* __restrict__ Z_real,
                                const float* __restrict__ Z_imag,
                                const int*   __restrict__ steps_p,
                                float4* __restrict__ out)
{
    if (threadIdx.x != 0 || blockIdx.x != 0) return;

    // Hoist all loads (max MLP on the cold path).
    const float wF   = __ldg(omega_mean);
    const float Kc   = __ldg(coupling);
    const float dltF = __ldg(delta);
    const float zr0  = __ldg(Z_real);
    const float zi0  = __ldg(Z_imag);
    const int   n    = __ldg(steps_p);

    const float KhF = 0.5f * Kc;
    const float c   = DT * wF;
    const float csq = c * c;
    const float g   = DT * KhF;
    const float lin = DT * (KhF - dltF);      // b0 - 1
    const float b0  = 1.0f + lin;

    const float s0 = __fmaf_rn(zr0, zr0, zi0 * zi0);

    const float discF = __fmaf_rn(-c, c, 1.0f);
    bool ok = (n >= 20000) && (s0 > 1e-30f) && (g > 0.0f) &&
              (discF > 1e-4f) && (fabsf(c) < 0.0499f);  // series validity

    // ---- b_inf, s_inf (float; cancellation-free identity) ----
    float b_inf = 0.0f, s_inf = 0.0f;
    if (ok) {
        b_inf = sqrtf(discF);
        const float diff = lin + __fdividef(csq, 1.0f + b_inf); // b0 - b_inf
        s_inf = __fdividef(diff, g);
        if (s_inf > 1e-12f) {
            const float rho = 1.0f - 2.0f * g * s_inf * b_inf;
            ok = (rho > 0.0f) && (rho < 1.0f) &&
                 ((float)n * (1.0f - rho) > 60.0f);     // rho^n -> 0
        } else ok = false;
    }

    const float A = __fmaf_rn(b0, b0, csq);
    const float B = 2.0f * b0 * g;
    const float C = g * g;

    float r1L = 0.0f, r2 = 0.0f, u0 = 0.0f, xq = 0.0f, xr = 0.0f;
    if (ok) {
        const float L1c = __fmaf_rn(b0, b_inf, csq);    // b0*b_inf + c^2
        r1L = __fdividef(L1c, g * b_inf);
        r2  = __fdividef(B, C) - s_inf;
        const float L1s0 = __fmaf_rn(-g * b_inf, s0, L1c);
        u0  = __fdividef(c * g * (s0 - s_inf), L1s0);
        xq  = __fdividef(s0 - s_inf, r1L - s0);
        xr  = __fdividef(s0 - s_inf, r2 - s0);
        ok = (fabsf(u0) < 0.02f) && (fabsf(xq) < 0.1f) && (fabsf(xr) < 0.1f) &&
             (s0 < 0.5f * r1L) && (s0 < 0.5f * r2) && (L1s0 > 1e-10f);
    }

    float4 res;

    if (ok) {
        // ---- main rational integral: exact partial fractions ----
        const float K0  = __fdividef(-c, b_inf * C);
        const float dQR = r1L - r2;
        const float P   = __fdividef(-1.0f, r1L * r2);
        const float Q   = __fdividef( 1.0f, r1L * dQR);
        const float Rc  = __fdividef( 1.0f, r2  * dQR);

        float sumPsi = K0 * ( P  * __logf(__fdividef(s_inf, s0))
                            - Q  * log1p_small_f(xq)
                            + Rc * log1p_small_f(xr) );

        // ---- modified-field correction: (1/2)∫ psi D'/D ds, 3-pt Gauss ----
        {
            const float mid  = 0.5f * (s0 + s_inf);
            const float half = 0.5f * (s_inf - s0);
            const float nd   = 0.77459666924f * half;
            const float sg[3] = { mid - nd, mid, mid + nd };
            const float wg[3] = { 5.0f / 9.0f, 8.0f / 9.0f, 5.0f / 9.0f };
            const float A1  = A - 1.0f;
            const float L1c = __fmaf_rn(b0, b_inf, csq);
            float acc = 0.0f;
            #pragma unroll
            for (int i = 0; i < 3; ++i) {
                const float s  = sg[i];
                const float L1 = __fmaf_rn(-g * b_inf, s, L1c);
                const float L2 = __fmaf_rn(C, s, C * s_inf - B);  // C (s - r2)
                const float Dp = __fmaf_rn(s, __fmaf_rn(3.0f * C, s, -2.0f * B), A1);
                acc += wg[i] * __fdividef(Dp, s * L1 * L2);
            }
            sumPsi += (-0.5f * c * g) * acc * half;
        }

        // ---- EM endpoint ----
        sumPsi -= 0.5f * atan_small_f(u0);

        // ---- phase: n*phi_inf with phi_inf = -asin(c) = -(c + t) ----
        // t = c^3 * (1/6 + 3c^2/40 + 15c^4/336); trunc err ~ 0.03*c^9 < 6e-14
        const float nf = (float)n;                       // exact (n < 2^24)
        float t;
        {
            const float c2 = c * c;
            float p = 15.0f / 336.0f;
            p = __fmaf_rn(p, c2, 3.0f / 40.0f);
            p = __fmaf_rn(p, c2, 1.0f / 6.0f);
            t = c * c2 * p;
        }
        const float P_hi = nf * c;                       // big term (~1000)
        const float P_lo = __fmaf_rn(nf, c, -P_hi);      // exact residual

        float theta0F;
        if (zi0 == 0.0f && zr0 > 0.0f) theta0F = 0.0f;
        else                           theta0F = atan2f(zi0, zr0);

        // theta = theta0 - (P_hi + P_lo + n*t) + sumPsi ; keep P_hi separate.
        const float small = ((theta0F - P_lo) - nf * t) + sumPsi;

        // ---- Cody-Waite mod 2*pi with float pair (exact-fma folding) ----
        const float TWOPI_HI = 6.2831854820251465f;      // float(2*pi)
        const float TWOPI_LO = -1.7484556000744876e-7f;  // 2*pi - TWOPI_HI
        const float INV2PI   = 0.15915494309f;
        const float kf = rintf(__fmaf_rn(-P_hi, -1.0f, small - 2.0f * P_hi) == 0.0f
                               ? 0.0f : (small - P_hi) * INV2PI);
        // (the ternary is never-taken noise-free form; compute directly:)
        const float kf2 = rintf((small - P_hi) * INV2PI);
        const float a   = __fmaf_rn(-kf2, TWOPI_HI, -P_hi);  // exact-ish big fold
        const float r   = (a + small) - kf2 * TWOPI_LO;

        const float Rf   = sqrtf(s_inf);
        const float PsiF = r;                            // in (-pi, pi]
        float sa, ca;
        __sincosf(PsiF, &sa, &ca);
        res.x = Rf;
        res.y = PsiF;
        res.z = Rf * ca;
        res.w = Rf * sa;
        (void)kf;
    } else {
        // ---- exact fallback: full float iteration of the original map ----
        float s = s0, zr = zr0, zi = zi0;
        #pragma unroll 16
        for (int i = 0; i < n; ++i) {
            const float b = __fmaf_rn(-g, s, b0);
            const float m = __fmaf_rn(b, b, csq);
            const float czr = c * zr;
            const float czi = c * zi;
            const float nzr = __fmaf_rn(b, zr, czi);
            const float nzi = __fmaf_rn(b, zi, -czr);
            s  = s * m;
            zr = nzr;
            zi = nzi;
        }
        res.x = sqrtf(__fmaf_rn(zr, zr, zi * zi));
        res.y = atan2f(zi, zr);
        res.z = zr;
        res.w = zi;
    }

    *out = res;   // single STG.128
}

extern "C" void kernel_launch(void* const* d_in, const int* in_sizes, int n_in,
                              void* d_out, int out_size)
{
    (void)in_sizes; (void)n_in; (void)out_size;
    const float* omega_mean = (const float*)d_in[0];
    const float* coupling   = (const float*)d_in[1];
    const float* delta      = (const float*)d_in[2];
    const float* Z_real     = (const float*)d_in[3];
    const float* Z_imag     = (const float*)d_in[4];
    const int*   steps      = (const int*)  d_in[5];
    float4* out = (float4*)d_out;

    kuramoto_kernel<<<1, 1>>>(omega_mean, coupling, delta, Z_real, Z_imag, steps, out);
}